// round 1
// baseline (speedup 1.0000x reference)
#include <cuda_runtime.h>
#include <math.h>

#define BB 32
#define CC 64
#define HH 128
#define WW 128
#define QD 8
#define NEGV (-1e4f)

// Channels-last scratch: [b,h,w,ch]
__device__ float g_Qt[BB*HH*WW*QD];   // 16.8 MB
__device__ float g_Kt[BB*HH*WW*QD];   // 16.8 MB
__device__ float g_Vt[BB*HH*WW*CC];   // 134 MB
__device__ float g_Ot[BB*HH*WW*CC];   // 134 MB accumulator

__device__ __forceinline__ float softplus_f(float v) {
    return fmaxf(v, 0.f) + log1pf(expf(-fabsf(v)));
}

// ---------------------------------------------------------------------------
// Stage 1: per-(b,h) row block.
//   - projections Q,K (softplus), V from x row
//   - row attention: E_W[w,k] = sum_q Q[q,w]K[q,k]; out_W[c,w] = sum_k V[c,k]E_W[w,k]
//   - writes Qt/Kt/Vt channels-last, out_W -> g_Ot
// Dynamic smem layout (floats):
//   XS  @0      : 8320  (x tile [c*128+w]; later reused as ES (16x128) then OS (128x65))
//   WS  @8320   : 5120  (80 x 64 weights: wq rows 0-7, wk 8-15, wv 16-79)
//   BS  @13440  : 80    (biases)
//   QS  @13520  : 1024  ([q*128+w])
//   KS  @14544  : 1024
//   VS  @15568  : 8256  ([c*129+w])
// total 23824 floats = 95296 B
// ---------------------------------------------------------------------------
#define S1_SMEM_FLOATS 23824

__global__ __launch_bounds__(256, 2) void cc_row_kernel(
    const float* __restrict__ x,
    const float* __restrict__ wq, const float* __restrict__ bq,
    const float* __restrict__ wk, const float* __restrict__ bk,
    const float* __restrict__ wv, const float* __restrict__ bv)
{
    extern __shared__ float sm[];
    float* XS = sm;
    float* WS = sm + 8320;
    float* BS = sm + 13440;
    float* QS = sm + 13520;
    float* KS = sm + 14544;
    float* VS = sm + 15568;
    float* ES = sm;        // reuses XS after projections
    float* OS = sm;        // reuses XS at the end (128x65)

    const int b = blockIdx.y;
    const int h = blockIdx.x;
    const int tid = threadIdx.x;

    // load x row: x[b, c, h, :]
    const float* xrow = x + ((b*CC)*HH + h)*WW;
    for (int i = tid; i < CC*WW; i += 256) {
        int c = i >> 7, w = i & 127;
        XS[c*128 + w] = xrow[c*HH*WW + w];
    }
    // weights + biases
    for (int i = tid; i < QD*CC; i += 256) WS[i]        = wq[i];
    for (int i = tid; i < QD*CC; i += 256) WS[512 + i]  = wk[i];
    for (int i = tid; i < CC*CC; i += 256) WS[1024 + i] = wv[i];
    if (tid < QD)               BS[tid] = bq[tid];
    else if (tid < 2*QD)        BS[tid] = bk[tid - QD];
    else if (tid < 2*QD + CC)   BS[tid] = bv[tid - 2*QD];
    __syncthreads();

    // ---- projections: 80 output rows x 128 w ----
    {
        const int ogrp = tid >> 5;        // 0..7 -> 10 rows each
        const int w0   = (tid & 31) << 2; // 0..124
        float acc[10][4];
        #pragma unroll
        for (int i = 0; i < 10; i++) {
            float bb = BS[ogrp*10 + i];
            acc[i][0]=bb; acc[i][1]=bb; acc[i][2]=bb; acc[i][3]=bb;
        }
        #pragma unroll 4
        for (int c = 0; c < CC; c++) {
            float4 xv = *(const float4*)&XS[c*128 + w0];
            #pragma unroll
            for (int i = 0; i < 10; i++) {
                float wv_ = WS[(ogrp*10 + i)*64 + c];
                acc[i][0] += wv_*xv.x; acc[i][1] += wv_*xv.y;
                acc[i][2] += wv_*xv.z; acc[i][3] += wv_*xv.w;
            }
        }
        #pragma unroll
        for (int i = 0; i < 10; i++) {
            int o = ogrp*10 + i;
            #pragma unroll
            for (int j = 0; j < 4; j++) {
                float v = acc[i][j];
                if (o < 8)        QS[o*128 + w0 + j]      = softplus_f(v);
                else if (o < 16)  KS[(o-8)*128 + w0 + j]  = softplus_f(v);
                else              VS[(o-16)*129 + w0 + j] = v;
            }
        }
    }
    __syncthreads();   // XS now free; QS/KS/VS valid

    // ---- write channels-last Qt/Kt/Vt ----
    {
        float* qtb = g_Qt + ((b*HH + h)*WW)*QD;
        float* ktb = g_Kt + ((b*HH + h)*WW)*QD;
        for (int i = tid; i < WW*QD; i += 256) {
            int w = i >> 3, q = i & 7;
            qtb[i] = QS[q*128 + w];
            ktb[i] = KS[q*128 + w];
        }
        float* vtb = g_Vt + ((b*HH + h)*WW)*CC;
        for (int i = tid; i < WW*CC; i += 256) {
            int w = i >> 6, c = i & 63;
            vtb[i] = VS[c*129 + w];
        }
    }

    // ---- row attention ----
    float accO[4][8];
    #pragma unroll
    for (int i = 0; i < 4; i++)
        #pragma unroll
        for (int j = 0; j < 8; j++) accO[i][j] = 0.f;

    const int c0  = (tid >> 4) * 4;   // out tile: 4 c
    const int w0o = (tid & 15) * 8;   //           8 w
    const int kke = tid >> 4;         // E tile: this thread's k-within-tile
    const int we  = (tid & 15) * 8;   //         8 w

    for (int kt = 0; kt < WW; kt += 16) {
        // E tile: ES[kk][w] = sum_q Q[q][w]*K[q][kt+kk]
        float e[8];
        #pragma unroll
        for (int j = 0; j < 8; j++) e[j] = 0.f;
        #pragma unroll
        for (int q = 0; q < 8; q++) {
            float kval = KS[q*128 + kt + kke];
            float4 a  = *(const float4*)&QS[q*128 + we];
            float4 b4 = *(const float4*)&QS[q*128 + we + 4];
            e[0]+=kval*a.x;  e[1]+=kval*a.y;  e[2]+=kval*a.z;  e[3]+=kval*a.w;
            e[4]+=kval*b4.x; e[5]+=kval*b4.y; e[6]+=kval*b4.z; e[7]+=kval*b4.w;
        }
        __syncthreads();   // prior ES readers done
        #pragma unroll
        for (int j = 0; j < 8; j++) ES[kke*128 + we + j] = e[j];
        __syncthreads();

        #pragma unroll
        for (int kk = 0; kk < 16; kk++) {
            int k = kt + kk;
            float v0 = VS[(c0+0)*129 + k];
            float v1 = VS[(c0+1)*129 + k];
            float v2 = VS[(c0+2)*129 + k];
            float v3 = VS[(c0+3)*129 + k];
            float4 ea = *(const float4*)&ES[kk*128 + w0o];
            float4 eb = *(const float4*)&ES[kk*128 + w0o + 4];
            float ev[8] = {ea.x,ea.y,ea.z,ea.w,eb.x,eb.y,eb.z,eb.w};
            #pragma unroll
            for (int j = 0; j < 8; j++) {
                accO[0][j] += v0*ev[j];
                accO[1][j] += v1*ev[j];
                accO[2][j] += v2*ev[j];
                accO[3][j] += v3*ev[j];
            }
        }
    }
    __syncthreads();
    // stage out_W to OS[w][c] (stride 65), then coalesced global write
    #pragma unroll
    for (int j = 0; j < 8; j++)
        #pragma unroll
        for (int i = 0; i < 4; i++)
            OS[(w0o + j)*65 + c0 + i] = accO[i][j];
    __syncthreads();
    float* otb = g_Ot + ((b*HH + h)*WW)*CC;
    for (int i = tid; i < WW*CC; i += 256) {
        int w = i >> 6, c = i & 63;
        otb[i] = OS[w*65 + c];
    }
}

// ---------------------------------------------------------------------------
// Stage 2: per-(b,w) column block.
//   E_H[h,k] = sum_q Q[q,h]K[q,k] + NEG*(h==k); out_H[c,h] = sum_k V[c,k]E_H[h,k]
//   g_Ot[b,h,w,:] += out_H
// smem (floats): OS @0: 8320 (ES 16x128 overlaps), QS @8320: 1056 ([q*132+h]),
//                KS @9376: 1056, VS @10432: 8256 ([c*129+k])  -> 18688 = 74752 B
// ---------------------------------------------------------------------------
#define S2_SMEM_FLOATS 18688

__global__ __launch_bounds__(256, 2) void cc_col_kernel()
{
    extern __shared__ float sm[];
    float* OS = sm;
    float* ES = sm;
    float* QS = sm + 8320;
    float* KS = sm + 9376;
    float* VS = sm + 10432;

    const int b = blockIdx.y;
    const int w = blockIdx.x;
    const int tid = threadIdx.x;

    // load Q/K columns [h][q] -> [q*132+h]
    {
        const float* qsrc = g_Qt + (b*HH*WW + w)*QD;
        const float* ksrc = g_Kt + (b*HH*WW + w)*QD;
        for (int i = tid; i < HH*QD; i += 256) {
            int h = i >> 3, q = i & 7;
            QS[q*132 + h] = qsrc[h*WW*QD + q];
            KS[q*132 + h] = ksrc[h*WW*QD + q];
        }
        const float* vsrc = g_Vt + (b*HH*WW + w)*CC;
        for (int i = tid; i < HH*CC; i += 256) {
            int k = i >> 6, c = i & 63;
            VS[c*129 + k] = vsrc[k*WW*CC + c];
        }
    }
    __syncthreads();

    float accO[4][8];
    #pragma unroll
    for (int i = 0; i < 4; i++)
        #pragma unroll
        for (int j = 0; j < 8; j++) accO[i][j] = 0.f;

    const int c0  = (tid >> 4) * 4;
    const int h0o = (tid & 15) * 8;
    const int kke = tid >> 4;
    const int he  = (tid & 15) * 8;

    for (int kt = 0; kt < HH; kt += 16) {
        float e[8];
        #pragma unroll
        for (int j = 0; j < 8; j++) e[j] = 0.f;
        #pragma unroll
        for (int q = 0; q < 8; q++) {
            float kval = KS[q*132 + kt + kke];
            float4 a  = *(const float4*)&QS[q*132 + he];
            float4 b4 = *(const float4*)&QS[q*132 + he + 4];
            e[0]+=kval*a.x;  e[1]+=kval*a.y;  e[2]+=kval*a.z;  e[3]+=kval*a.w;
            e[4]+=kval*b4.x; e[5]+=kval*b4.y; e[6]+=kval*b4.z; e[7]+=kval*b4.w;
        }
        // masked diagonal: entry (k = kt+kke, h = he+j), add NEG when h == k
        {
            int k = kt + kke;
            int dj = k - he;
            if (dj >= 0 && dj < 8) e[dj] += NEGV;
        }
        __syncthreads();
        #pragma unroll
        for (int j = 0; j < 8; j++) ES[kke*128 + he + j] = e[j];
        __syncthreads();

        #pragma unroll
        for (int kk = 0; kk < 16; kk++) {
            int k = kt + kk;
            float v0 = VS[(c0+0)*129 + k];
            float v1 = VS[(c0+1)*129 + k];
            float v2 = VS[(c0+2)*129 + k];
            float v3 = VS[(c0+3)*129 + k];
            float4 ea = *(const float4*)&ES[kk*128 + h0o];
            float4 eb = *(const float4*)&ES[kk*128 + h0o + 4];
            float ev[8] = {ea.x,ea.y,ea.z,ea.w,eb.x,eb.y,eb.z,eb.w};
            #pragma unroll
            for (int j = 0; j < 8; j++) {
                accO[0][j] += v0*ev[j];
                accO[1][j] += v1*ev[j];
                accO[2][j] += v2*ev[j];
                accO[3][j] += v3*ev[j];
            }
        }
    }
    __syncthreads();
    #pragma unroll
    for (int j = 0; j < 8; j++)
        #pragma unroll
        for (int i = 0; i < 4; i++)
            OS[(h0o + j)*65 + c0 + i] = accO[i][j];
    __syncthreads();

    // g_Ot[b,h,w,c] += out_H  (coalesced 256B chunks per h)
    float* ob = g_Ot + (b*HH*WW + w)*CC;
    for (int i = tid; i < HH*CC; i += 256) {
        int h = i >> 6, c = i & 63;
        int gi = h*WW*CC + c;
        ob[gi] = ob[gi] + OS[h*65 + c];
    }
}

// ---------------------------------------------------------------------------
// Stage 3: per-(b,h): out[b,c,h,w] = gamma * Ot[b,h,w,c] + x[b,c,h,w]
// ---------------------------------------------------------------------------
__global__ __launch_bounds__(256) void cc_final_kernel(
    const float* __restrict__ x, const float* __restrict__ gamma,
    float* __restrict__ out)
{
    __shared__ float OS[128*65];   // 33.3 KB
    const int b = blockIdx.y;
    const int h = blockIdx.x;
    const int tid = threadIdx.x;
    const float g = gamma[0];

    const float* src = g_Ot + ((b*HH + h)*WW)*CC;
    for (int i = tid; i < WW*CC; i += 256) {
        int w = i >> 6, c = i & 63;
        OS[w*65 + c] = src[i];
    }
    __syncthreads();
    for (int i = tid; i < CC*WW; i += 256) {
        int c = i >> 7, w = i & 127;
        int gi = ((b*CC + c)*HH + h)*WW + w;
        out[gi] = g * OS[w*65 + c] + x[gi];
    }
}

// ---------------------------------------------------------------------------
extern "C" void kernel_launch(void* const* d_in, const int* in_sizes, int n_in,
                              void* d_out, int out_size)
{
    const float* x     = (const float*)d_in[0];
    const float* wq    = (const float*)d_in[1];
    const float* bq    = (const float*)d_in[2];
    const float* wk    = (const float*)d_in[3];
    const float* bk    = (const float*)d_in[4];
    const float* wv    = (const float*)d_in[5];
    const float* bv    = (const float*)d_in[6];
    const float* gamma = (const float*)d_in[7];
    float* out = (float*)d_out;

    (void)in_sizes; (void)n_in; (void)out_size;

    cudaFuncSetAttribute(cc_row_kernel, cudaFuncAttributeMaxDynamicSharedMemorySize,
                         S1_SMEM_FLOATS * (int)sizeof(float));
    cudaFuncSetAttribute(cc_col_kernel, cudaFuncAttributeMaxDynamicSharedMemorySize,
                         S2_SMEM_FLOATS * (int)sizeof(float));

    cc_row_kernel<<<dim3(HH, BB), 256, S1_SMEM_FLOATS * sizeof(float)>>>(
        x, wq, bq, wk, bk, wv, bv);
    cc_col_kernel<<<dim3(WW, BB), 256, S2_SMEM_FLOATS * sizeof(float)>>>();
    cc_final_kernel<<<dim3(HH, BB), 256>>>(x, gamma, out);
}

// round 4
// speedup vs baseline: 2.3366x; 2.3366x over previous
#include <cuda_runtime.h>
#include <math.h>

#define BB 32
#define CC 64
#define HH 128
#define WW 128
#define QD 8
#define NEGV (-1e4f)

// scratch (channels-last): Qt/Kt [b,h,w,q], Vt/Ot [b,h,w,c], MW [b,h,c,q]
__device__ float g_Qt[BB*HH*WW*QD];       // 16.8 MB
__device__ float g_Kt[BB*HH*WW*QD];       // 16.8 MB
__device__ float g_Vt[BB*HH*WW*CC];       // 134 MB
__device__ float g_Ot[BB*HH*WW*CC];       // 134 MB (OH contribution incl. NEG*V)
__device__ float g_MW[BB*HH*CC*QD];       // 8.4 MB

__device__ __forceinline__ float softplus_f(float v) {
    return fmaxf(v, 0.f) + log1pf(expf(-fabsf(v)));
}

// ---------------------------------------------------------------------------
// P1: per (b,h) row. Projections Q,K (softplus), V. M_W = V*K^T over w.
// Writes Qt,Kt,Vt channels-last and MW.
// smem (floats): XS@0:8192  WS@8192:5120  BS@13312:96
//                QS@13408:1056  KS@14464:1056  VS@15520:8448  -> 23968 = 95872 B
// ---------------------------------------------------------------------------
#define S1_SMEM_FLOATS 23968

__global__ __launch_bounds__(256, 2) void cc_p1_kernel(
    const float* __restrict__ x,
    const float* __restrict__ wq, const float* __restrict__ bq,
    const float* __restrict__ wk, const float* __restrict__ bk,
    const float* __restrict__ wv, const float* __restrict__ bv)
{
    extern __shared__ float sm[];
    float* XS = sm;
    float* WS = sm + 8192;
    float* BS = sm + 13312;
    float* QS = sm + 13408;
    float* KS = sm + 14464;
    float* VS = sm + 15520;

    const int b = blockIdx.y;
    const int h = blockIdx.x;
    const int tid = threadIdx.x;

    // x row [c][w]
    const float* xrow = x + ((b*CC)*HH + h)*WW;
    for (int i = tid; i < CC*WW; i += 256) {
        int c = i >> 7, w = i & 127;
        XS[c*128 + w] = xrow[c*HH*WW + w];
    }
    for (int i = tid; i < QD*CC; i += 256) WS[i]        = wq[i];
    for (int i = tid; i < QD*CC; i += 256) WS[512 + i]  = wk[i];
    for (int i = tid; i < CC*CC; i += 256) WS[1024 + i] = wv[i];
    if (tid < QD)               BS[tid] = bq[tid];
    else if (tid < 2*QD)        BS[tid] = bk[tid - QD];
    else if (tid < 2*QD + CC)   BS[tid] = bv[tid - 2*QD];
    __syncthreads();

    // projections: 80 outputs x 128 w; thread = (ogrp of 10 outputs) x (4 w)
    {
        const int ogrp = tid >> 5;
        const int w0   = (tid & 31) << 2;
        float acc[10][4];
        #pragma unroll
        for (int i = 0; i < 10; i++) {
            float bb = BS[ogrp*10 + i];
            acc[i][0]=bb; acc[i][1]=bb; acc[i][2]=bb; acc[i][3]=bb;
        }
        #pragma unroll 4
        for (int c = 0; c < CC; c++) {
            float4 xv = *(const float4*)&XS[c*128 + w0];
            #pragma unroll
            for (int i = 0; i < 10; i++) {
                float wv_ = WS[(ogrp*10 + i)*64 + c];
                acc[i][0] += wv_*xv.x; acc[i][1] += wv_*xv.y;
                acc[i][2] += wv_*xv.z; acc[i][3] += wv_*xv.w;
            }
        }
        #pragma unroll
        for (int i = 0; i < 10; i++) {
            int o = ogrp*10 + i;
            #pragma unroll
            for (int j = 0; j < 4; j++) {
                float v = acc[i][j];
                if (o < 8)        QS[o*132 + w0 + j]      = softplus_f(v);
                else if (o < 16)  KS[(o-8)*132 + w0 + j]  = softplus_f(v);
                else              VS[(o-16)*132 + w0 + j] = v;
            }
        }
    }
    __syncthreads();

    // channels-last global writes
    {
        float* qtb = g_Qt + (b*HH + h)*WW*QD;
        float* ktb = g_Kt + (b*HH + h)*WW*QD;
        for (int i = tid; i < WW*QD; i += 256) {
            int w = i >> 3, q = i & 7;
            qtb[i] = QS[q*132 + w];
            ktb[i] = KS[q*132 + w];
        }
        float* vtb = g_Vt + (b*HH + h)*WW*CC;
        for (int i = tid; i < WW*CC; i += 256) {
            int w = i >> 6, c = i & 63;
            vtb[i] = VS[c*132 + w];
        }
    }

    // M_W(c,q) = sum_w V(c,w)*K(q,w) ; thread -> (c = tid>>2, q in {tid&3, tid&3+4})
    {
        const int c  = tid >> 2;
        const int q0 = tid & 3;
        const int q1 = q0 + 4;
        float a0 = 0.f, a1 = 0.f;
        #pragma unroll 8
        for (int w = 0; w < WW; w += 4) {
            float4 v  = *(const float4*)&VS[c*132 + w];
            float4 k0 = *(const float4*)&KS[q0*132 + w];
            float4 k1 = *(const float4*)&KS[q1*132 + w];
            a0 = fmaf(v.x,k0.x, fmaf(v.y,k0.y, fmaf(v.z,k0.z, fmaf(v.w,k0.w, a0))));
            a1 = fmaf(v.x,k1.x, fmaf(v.y,k1.y, fmaf(v.z,k1.z, fmaf(v.w,k1.w, a1))));
        }
        float* mwb = g_MW + ((b*HH + h)*CC + c)*QD;
        mwb[q0] = a0;
        mwb[q1] = a1;
    }
}

// ---------------------------------------------------------------------------
// P2: per (b,w) column. M_H = V*K^T over h, then
//     OH(c,h) = sum_q M_H(c,q)*Q(q,h) + NEG*V(c,h) -> Ot[b,h,w,c]
// smem: VS2@0:8256 ([c*129+h])  KS2@8256:1056  QS2@9312:1056  MHS@10368:512
//       -> 10880 floats = 43520 B
// ---------------------------------------------------------------------------
#define S2_SMEM_FLOATS 10880

__global__ __launch_bounds__(256, 4) void cc_p2_kernel()
{
    extern __shared__ float sm[];
    float* VS2 = sm;
    float* KS2 = sm + 8256;
    float* QS2 = sm + 9312;
    float* MHS = sm + 10368;

    const int b = blockIdx.y;
    const int w = blockIdx.x;
    const int tid = threadIdx.x;

    // loads (all coalesced in global)
    {
        const float* vsrc = g_Vt + (size_t)b*HH*WW*CC + (size_t)w*CC;  // (h,c) at h*8192+c
        for (int i = tid; i < HH*CC; i += 256) {
            int h = i >> 6, c = i & 63;
            VS2[c*129 + h] = vsrc[(size_t)h*WW*CC + c];
        }
        const float* ksrc = g_Kt + (size_t)b*HH*WW*QD + (size_t)w*QD;
        const float* qsrc = g_Qt + (size_t)b*HH*WW*QD + (size_t)w*QD;
        for (int i = tid; i < HH*QD; i += 256) {
            int h = i >> 3, q = i & 7;
            KS2[q*132 + h] = ksrc[(size_t)h*WW*QD + q];
            QS2[q*132 + h] = qsrc[(size_t)h*WW*QD + q];
        }
    }
    __syncthreads();

    // M_H
    {
        const int c  = tid >> 2;
        const int q0 = tid & 3;
        const int q1 = q0 + 4;
        float a0 = 0.f, a1 = 0.f;
        #pragma unroll 8
        for (int h = 0; h < HH; h++) {
            float v = VS2[c*129 + h];
            a0 = fmaf(v, KS2[q0*132 + h], a0);
            a1 = fmaf(v, KS2[q1*132 + h], a1);
        }
        MHS[c*8 + q0] = a0;
        MHS[c*8 + q1] = a1;
    }
    __syncthreads();

    // OH and write to Ot (float4 per (h, 4c))
    {
        const int c0 = (tid >> 4) * 4;
        const int h0 = (tid & 15) * 8;
        float m[4][8];
        #pragma unroll
        for (int i = 0; i < 4; i++)
            #pragma unroll
            for (int q = 0; q < 8; q++) m[i][q] = MHS[(c0+i)*8 + q];

        float* obase = g_Ot + (size_t)b*HH*WW*CC + (size_t)w*CC + c0;
        #pragma unroll
        for (int j = 0; j < 8; j++) {
            int h = h0 + j;
            float qv[8];
            #pragma unroll
            for (int q = 0; q < 8; q++) qv[q] = QS2[q*132 + h];
            float4 o;
            float* op = &o.x;
            #pragma unroll
            for (int i = 0; i < 4; i++) {
                float acc = NEGV * VS2[(c0+i)*129 + h];
                #pragma unroll
                for (int q = 0; q < 8; q++) acc = fmaf(m[i][q], qv[q], acc);
                op[i] = acc;
            }
            *(float4*)(obase + (size_t)h*WW*CC) = o;
        }
    }
}

// ---------------------------------------------------------------------------
// P3: per (b,h): out = gamma*(Ot + MW*Q) + x
// smem: OS3@0:8256 ([c*129+w])  QS3@8256:1056  -> 9312 floats = 37248 B
// ---------------------------------------------------------------------------
#define S3_SMEM_FLOATS 9312

__global__ __launch_bounds__(256, 4) void cc_p3_kernel(
    const float* __restrict__ x, const float* __restrict__ gamma,
    float* __restrict__ out)
{
    extern __shared__ float sm[];
    float* OS3 = sm;
    float* QS3 = sm + 8256;

    const int b = blockIdx.y;
    const int h = blockIdx.x;
    const int tid = threadIdx.x;
    const float g = gamma[0];

    {
        const float* osrc = g_Ot + (size_t)(b*HH + h)*WW*CC;   // wait: Ot is [b,h,w,c]
        // Ot[b,h,w,c] = ((b*HH+h)*WW + w)*CC + c
        for (int i = tid; i < WW*CC; i += 256) {
            int w = i >> 6, c = i & 63;
            OS3[c*129 + w] = osrc[i];
        }
        const float* qsrc = g_Qt + (size_t)(b*HH + h)*WW*QD;
        for (int i = tid; i < WW*QD; i += 256) {
            int w = i >> 3, q = i & 7;
            QS3[q*132 + w] = qsrc[i];
        }
    }

    // MW -> regs
    const int c0 = (tid >> 4) * 4;
    const int w0 = (tid & 15) * 4;
    float m[4][8];
    {
        const float* mwb = g_MW + ((size_t)(b*HH + h)*CC + c0)*QD;
        #pragma unroll
        for (int i = 0; i < 4; i++)
            #pragma unroll
            for (int q = 0; q < 8; q++) m[i][q] = mwb[i*QD + q];
    }
    __syncthreads();

    // two float4 groups per thread: w0..w0+3 and w0+64..w0+67
    #pragma unroll
    for (int j2 = 0; j2 < 2; j2++) {
        const int wb = w0 + 64*j2;
        float s[4][4];
        #pragma unroll
        for (int dw = 0; dw < 4; dw++) {
            int w = wb + dw;
            float qv[8];
            #pragma unroll
            for (int q = 0; q < 8; q++) qv[q] = QS3[q*132 + w];
            #pragma unroll
            for (int i = 0; i < 4; i++) {
                float acc = OS3[(c0+i)*129 + w];
                #pragma unroll
                for (int q = 0; q < 8; q++) acc = fmaf(m[i][q], qv[q], acc);
                s[i][dw] = acc;
            }
        }
        #pragma unroll
        for (int i = 0; i < 4; i++) {
            size_t gi = ((size_t)(b*CC + c0 + i)*HH + h)*WW + wb;
            float4 xv = *(const float4*)&x[gi];
            float4 o;
            o.x = fmaf(g, s[i][0], xv.x);
            o.y = fmaf(g, s[i][1], xv.y);
            o.z = fmaf(g, s[i][2], xv.z);
            o.w = fmaf(g, s[i][3], xv.w);
            *(float4*)&out[gi] = o;
        }
    }
}

// ---------------------------------------------------------------------------
extern "C" void kernel_launch(void* const* d_in, const int* in_sizes, int n_in,
                              void* d_out, int out_size)
{
    const float* x     = (const float*)d_in[0];
    const float* wq    = (const float*)d_in[1];
    const float* bq    = (const float*)d_in[2];
    const float* wk    = (const float*)d_in[3];
    const float* bk    = (const float*)d_in[4];
    const float* wv    = (const float*)d_in[5];
    const float* bv    = (const float*)d_in[6];
    const float* gamma = (const float*)d_in[7];
    float* out = (float*)d_out;

    (void)in_sizes; (void)n_in; (void)out_size;

    cudaFuncSetAttribute(cc_p1_kernel, cudaFuncAttributeMaxDynamicSharedMemorySize,
                         S1_SMEM_FLOATS * (int)sizeof(float));
    cudaFuncSetAttribute(cc_p2_kernel, cudaFuncAttributeMaxDynamicSharedMemorySize,
                         S2_SMEM_FLOATS * (int)sizeof(float));
    cudaFuncSetAttribute(cc_p3_kernel, cudaFuncAttributeMaxDynamicSharedMemorySize,
                         S3_SMEM_FLOATS * (int)sizeof(float));

    cc_p1_kernel<<<dim3(HH, BB), 256, S1_SMEM_FLOATS * sizeof(float)>>>(
        x, wq, bq, wk, bk, wv, bv);
    cc_p2_kernel<<<dim3(WW, BB), 256, S2_SMEM_FLOATS * sizeof(float)>>>();
    cc_p3_kernel<<<dim3(HH, BB), 256, S3_SMEM_FLOATS * sizeof(float)>>>(
        x, gamma, out);
}